// round 3
// baseline (speedup 1.0000x reference)
#include <cuda_runtime.h>
#include <string.h>

#define EPS 1e-5f

// ---------------- folded-weight scratch ------------------------------------
__device__ __align__(16) float g_W1t[512 * 192];   // [c][j], BN1 scale folded
__device__ __align__(16) float g_b1f[192];         // BN1 folded bias
__device__ __align__(16) float g_W4t[64 * 512];    // [d][c], BN2 scale folded
__device__ __align__(16) float g_c4f[512];         // BN2 folded bias

__global__ void prep_kernel(const float* __restrict__ W123, const float* __restrict__ b123,
                            const float* __restrict__ g123, const float* __restrict__ be123,
                            const float* __restrict__ m123, const float* __restrict__ v123,
                            const float* __restrict__ W4,   const float* __restrict__ b4,
                            const float* __restrict__ g4,   const float* __restrict__ be4,
                            const float* __restrict__ m4,   const float* __restrict__ v4)
{
    int idx = blockIdx.x * blockDim.x + threadIdx.x;
    if (idx < 512 * 192) {
        int c = idx / 192, j = idx % 192;
        float s = g123[j] * rsqrtf(v123[j] + EPS);
        g_W1t[c * 192 + j] = W123[j * 512 + c] * s;
    }
    int i2 = idx - 512 * 192;
    if (i2 >= 0 && i2 < 192) {
        float s = g123[i2] * rsqrtf(v123[i2] + EPS);
        g_b1f[i2] = (b123[i2] - m123[i2]) * s + be123[i2];
    }
    int i3 = idx - (512 * 192 + 192);
    if (i3 >= 0 && i3 < 64 * 512) {
        int d = i3 / 512, c = i3 % 512;
        float s = g4[c] * rsqrtf(v4[c] + EPS);
        g_W4t[d * 512 + c] = W4[c * 64 + d] * s;
    }
    int i4 = idx - (512 * 192 + 192 + 64 * 512);
    if (i4 >= 0 && i4 < 512) {
        float s = g4[i4] * rsqrtf(v4[i4] + EPS);
        g_c4f[i4] = (b4[i4] - m4[i4]) * s + be4[i4];
    }
}

// ---------------- helpers ---------------------------------------------------
__device__ __forceinline__ float2 ffma2(float2 a, float2 b, float2 c) {
    unsigned long long au, bu, cu, du;
    memcpy(&au, &a, 8); memcpy(&bu, &b, 8); memcpy(&cu, &c, 8);
    asm("fma.rn.f32x2 %0, %1, %2, %3;" : "=l"(du) : "l"(au), "l"(bu), "l"(cu));
    float2 d; memcpy(&d, &du, 8); return d;
}
__device__ __forceinline__ void cp_async16(float* smem_dst, const float* gsrc) {
    unsigned s = (unsigned)__cvta_generic_to_shared(smem_dst);
    asm volatile("cp.async.cg.shared.global [%0], [%1], 16;" :: "r"(s), "l"(gsrc));
}
__device__ __forceinline__ void cp_async4(float* smem_dst, const float* gsrc) {
    unsigned s = (unsigned)__cvta_generic_to_shared(smem_dst);
    asm volatile("cp.async.ca.shared.global [%0], [%1], 4;" :: "r"(s), "l"(gsrc));
}

// SMEM (floats):
//   sB  : [0, 12288)      2 x (32 k-rows x 192 cols)  GEMM1 weight tiles (double buf)
//                         reused: reduction region (first 3072), then W4 chunks (8192)
//   sA  : [12288, 13312)  2 x (32 k-rows x 16 rows)   xs tiles (double buf)
//   sATT: [13312, 14352)  4 x 260                     att[s][d*4+l]
#define SMF 14352

__global__ void __launch_bounds__(256, 3)
fused_kernel(const float* __restrict__ x, float* __restrict__ out)
{
    extern __shared__ float sm[];
    float* sB   = sm;
    float* sA   = sm + 12288;
    float* sATT = sm + 13312;

    const int t    = threadIdx.x;
    const int warp = t >> 5;
    const int g    = t & 31;
    const int s    = warp & 3;        // local sample 0..3
    const int kh   = warp >> 2;       // k-half 0/1
    const int n0   = blockIdx.x * 4;

    // ---- stage loaders: b-tile (2 halves x 16 k) + a-tile (xs gather) ----
    auto load_stage = [&](int st, int buf) {
        float* bd = sB + buf * 6144;
        #pragma unroll
        for (int h = 0; h < 2; h++) {
            const float* src = g_W1t + (h * 256 + st * 16) * 192;
            #pragma unroll
            for (int i = 0; i < 3; i++) {
                int q = t + i * 256;                  // [0,768) float4 chunks
                cp_async16(bd + h * 3072 + q * 4, src + q * 4);
            }
        }
        float* ad = sA + buf * 512;
        #pragma unroll
        for (int i = 0; i < 2; i++) {
            int idx = t + i * 256;                    // [0,512)
            int h  = idx >> 8;
            int r  = idx & 255;
            int kr = r >> 4, ss = (r >> 2) & 3, l = r & 3;
            const float* src = x + ((long)(n0 + ss) * 512 + h * 256 + st * 16 + kr) * 16
                                 + (l >> 1) * 8 + (l & 1) * 2;
            cp_async4(ad + (h * 16 + kr) * 16 + ss * 4 + l, src);
        }
        asm volatile("cp.async.commit_group;");
    };

    // ---- GEMM1: acc[4 rows][6 cols as 3 float2], K split across kh ----
    float2 acc[4][3];
    #pragma unroll
    for (int l = 0; l < 4; l++)
        #pragma unroll
        for (int p = 0; p < 3; p++) acc[l][p] = make_float2(0.f, 0.f);

    load_stage(0, 0);
    for (int st = 0; st < 16; st++) {
        if (st + 1 < 16) {
            load_stage(st + 1, (st + 1) & 1);
            asm volatile("cp.async.wait_group 1;");
        } else {
            asm volatile("cp.async.wait_group 0;");
        }
        __syncthreads();
        const float* bp = sB + (st & 1) * 6144 + kh * 3072;
        const float* ap = sA + (st & 1) * 512 + kh * 256 + s * 4;
        #pragma unroll 8
        for (int kk = 0; kk < 16; kk++) {
            float4 a  = *(const float4*)&ap[kk * 16];
            float2 b0 = *(const float2*)&bp[kk * 192 + 2 * g];
            float2 b1 = *(const float2*)&bp[kk * 192 + 2 * g + 64];
            float2 b2 = *(const float2*)&bp[kk * 192 + 2 * g + 128];
            float2 a0 = make_float2(a.x, a.x), a1 = make_float2(a.y, a.y);
            float2 a2 = make_float2(a.z, a.z), a3 = make_float2(a.w, a.w);
            acc[0][0] = ffma2(a0, b0, acc[0][0]);
            acc[0][1] = ffma2(a0, b1, acc[0][1]);
            acc[0][2] = ffma2(a0, b2, acc[0][2]);
            acc[1][0] = ffma2(a1, b0, acc[1][0]);
            acc[1][1] = ffma2(a1, b1, acc[1][1]);
            acc[1][2] = ffma2(a1, b2, acc[1][2]);
            acc[2][0] = ffma2(a2, b0, acc[2][0]);
            acc[2][1] = ffma2(a2, b1, acc[2][1]);
            acc[2][2] = ffma2(a2, b2, acc[2][2]);
            acc[3][0] = ffma2(a3, b0, acc[3][0]);
            acc[3][1] = ffma2(a3, b1, acc[3][1]);
            acc[3][2] = ffma2(a3, b2, acc[3][2]);
        }
        __syncthreads();
    }

    // ---- k-split reduction: kh=1 partials -> smem (reuse sB buf0), kh=0 adds
    float* red = sB;   // 4 samples x 4 rows x 192 cols = 3072 floats
    if (kh == 1) {
        #pragma unroll
        for (int l = 0; l < 4; l++)
            #pragma unroll
            for (int p = 0; p < 3; p++)
                *(float2*)&red[s * 768 + l * 192 + p * 64 + 2 * g] = acc[l][p];
    }
    __syncthreads();
    if (kh == 0) {
        #pragma unroll
        for (int l = 0; l < 4; l++)
            #pragma unroll
            for (int p = 0; p < 3; p++) {
                float2 o = *(const float2*)&red[s * 768 + l * 192 + p * 64 + 2 * g];
                acc[l][p].x += o.x; acc[l][p].y += o.y;
            }
    }
    __syncthreads();   // red reads done -> sB reusable for W4 chunks

    // ---- start W4 chunk 0 load (all threads), attention in parallel (kh=0)
    auto load_w4 = [&](int cc) {
        #pragma unroll
        for (int i = 0; i < 8; i++) {
            int q = t + i * 256;          // [0,2048) float4 chunks: 64d x 128c
            int d = q >> 5, c4 = q & 31;
            cp_async16(sB + d * 128 + c4 * 4, g_W4t + d * 512 + cc * 128 + c4 * 4);
        }
        asm volatile("cp.async.commit_group;");
    };
    load_w4(0);

    if (kh == 0) {
        // bias + relu
        float2 q2[4], k2[4], v2[4];
        float2 bb0 = *(const float2*)&g_b1f[2 * g];
        float2 bb1 = *(const float2*)&g_b1f[2 * g + 64];
        float2 bb2 = *(const float2*)&g_b1f[2 * g + 128];
        #pragma unroll
        for (int l = 0; l < 4; l++) {
            q2[l].x = fmaxf(acc[l][0].x + bb0.x, 0.f);
            q2[l].y = fmaxf(acc[l][0].y + bb0.y, 0.f);
            k2[l].x = fmaxf(acc[l][1].x + bb1.x, 0.f);
            k2[l].y = fmaxf(acc[l][1].y + bb1.y, 0.f);
            v2[l].x = fmaxf(acc[l][2].x + bb2.x, 0.f);
            v2[l].y = fmaxf(acc[l][2].y + bb2.y, 0.f);
        }
        // warp-local attention (L=4), butterfly over 64 channels
        float sc[16];
        #pragma unroll
        for (int l = 0; l < 4; l++)
            #pragma unroll
            for (int m = 0; m < 4; m++)
                sc[l * 4 + m] = q2[l].x * k2[m].x + q2[l].y * k2[m].y;
        #pragma unroll
        for (int off = 16; off > 0; off >>= 1)
            #pragma unroll
            for (int i = 0; i < 16; i++)
                sc[i] += __shfl_xor_sync(0xffffffffu, sc[i], off);

        #pragma unroll
        for (int l = 0; l < 4; l++) {
            float s0 = sc[l*4+0], s1 = sc[l*4+1], s2 = sc[l*4+2], s3 = sc[l*4+3];
            float mx = fmaxf(fmaxf(s0, s1), fmaxf(s2, s3));
            float e0 = __expf(s0 - mx), e1 = __expf(s1 - mx);
            float e2 = __expf(s2 - mx), e3 = __expf(s3 - mx);
            float inv = 1.f / (e0 + e1 + e2 + e3);
            float ax = (e0*v2[0].x + e1*v2[1].x + e2*v2[2].x + e3*v2[3].x) * inv;
            float ay = (e0*v2[0].y + e1*v2[1].y + e2*v2[2].y + e3*v2[3].y) * inv;
            sATT[s * 260 + (2*g)   * 4 + l] = ax;
            sATT[s * 260 + (2*g+1) * 4 + l] = ay;
        }
    }

    // ---- GEMM2 + epilogue in 4 c-chunks of 128 (W4 tile single-buffered in sB)
    for (int cc = 0; cc < 4; cc++) {
        asm volatile("cp.async.wait_group 0;");
        __syncthreads();   // chunk cc ready; sATT ready (cc==0)

        const int cbase = cc * 128 + kh * 64 + 2 * g;   // lane's first c (pair)
        float2 y[4];
        #pragma unroll
        for (int l = 0; l < 4; l++) y[l] = make_float2(0.f, 0.f);

        const float* attn = &sATT[s * 260];
        const float* wp = sB + kh * 64 + 2 * g;
        #pragma unroll 4
        for (int d = 0; d < 64; d++) {
            float4 a = *(const float4*)&attn[d * 4];
            float2 w = *(const float2*)&wp[d * 128];
            y[0] = ffma2(make_float2(a.x, a.x), w, y[0]);
            y[1] = ffma2(make_float2(a.y, a.y), w, y[1]);
            y[2] = ffma2(make_float2(a.z, a.z), w, y[2]);
            y[3] = ffma2(make_float2(a.w, a.w), w, y[3]);
        }
        __syncthreads();            // done reading sB chunk
        if (cc + 1 < 4) load_w4(cc + 1);

        // epilogue for these 2 channels: out = x + y + c4f
        float2 cf = *(const float2*)&g_c4f[cbase];
        const float4* xb = (const float4*)x   + ((long)(n0 + s) * 512 + cbase) * 4;
        float4*       ob = (float4*)out       + ((long)(n0 + s) * 512 + cbase) * 4;
        #pragma unroll
        for (int l = 0; l < 4; l++) {
            float yv = y[l].x + cf.x;
            float4 v = __ldg(&xb[l]);
            v.x += yv; v.y += yv; v.z += yv; v.w += yv;
            ob[l] = v;
        }
        #pragma unroll
        for (int l = 0; l < 4; l++) {
            float yv = y[l].y + cf.y;
            float4 v = __ldg(&xb[4 + l]);
            v.x += yv; v.y += yv; v.z += yv; v.w += yv;
            ob[4 + l] = v;
        }
    }
}

extern "C" void kernel_launch(void* const* d_in, const int* in_sizes, int n_in,
                              void* d_out, int out_size)
{
    const float* x    = (const float*)d_in[0];
    const float* W123 = (const float*)d_in[1];
    const float* b123 = (const float*)d_in[2];
    const float* g123 = (const float*)d_in[3];
    const float* be123= (const float*)d_in[4];
    const float* m123 = (const float*)d_in[5];
    const float* v123 = (const float*)d_in[6];
    const float* W4   = (const float*)d_in[7];
    const float* b4   = (const float*)d_in[8];
    const float* g4   = (const float*)d_in[9];
    const float* be4  = (const float*)d_in[10];
    const float* m4   = (const float*)d_in[11];
    const float* v4   = (const float*)d_in[12];

    int N = in_sizes[0] / (512 * 16);   // 2048

    prep_kernel<<<515, 256>>>(W123, b123, g123, be123, m123, v123,
                              W4, b4, g4, be4, m4, v4);

    cudaFuncSetAttribute(fused_kernel, cudaFuncAttributeMaxDynamicSharedMemorySize,
                         SMF * 4);
    fused_kernel<<<N / 4, 256, SMF * 4>>>(x, (float*)d_out);
}

// round 4
// speedup vs baseline: 1.3755x; 1.3755x over previous
#include <cuda_runtime.h>
#include <string.h>

#define EPS 1e-5f

// ---------------- folded-weight scratch ------------------------------------
__device__ __align__(16) float g_W1t[512 * 192];   // [c][j], BN1 scale folded
__device__ __align__(16) float g_b1f[192];         // BN1 folded bias
__device__ __align__(16) float g_W4t[64 * 512];    // [d][c], BN2 scale folded
__device__ __align__(16) float g_c4f[512];         // BN2 folded bias

__global__ void prep_kernel(const float* __restrict__ W123, const float* __restrict__ b123,
                            const float* __restrict__ g123, const float* __restrict__ be123,
                            const float* __restrict__ m123, const float* __restrict__ v123,
                            const float* __restrict__ W4,   const float* __restrict__ b4,
                            const float* __restrict__ g4,   const float* __restrict__ be4,
                            const float* __restrict__ m4,   const float* __restrict__ v4)
{
    int idx = blockIdx.x * blockDim.x + threadIdx.x;
    if (idx < 512 * 192) {
        int c = idx / 192, j = idx % 192;
        float s = g123[j] * rsqrtf(v123[j] + EPS);
        g_W1t[c * 192 + j] = W123[j * 512 + c] * s;
    }
    int i2 = idx - 512 * 192;
    if (i2 >= 0 && i2 < 192) {
        float s = g123[i2] * rsqrtf(v123[i2] + EPS);
        g_b1f[i2] = (b123[i2] - m123[i2]) * s + be123[i2];
    }
    int i3 = idx - (512 * 192 + 192);
    if (i3 >= 0 && i3 < 64 * 512) {
        int d = i3 / 512, c = i3 % 512;
        float s = g4[c] * rsqrtf(v4[c] + EPS);
        g_W4t[d * 512 + c] = W4[c * 64 + d] * s;
    }
    int i4 = idx - (512 * 192 + 192 + 64 * 512);
    if (i4 >= 0 && i4 < 512) {
        float s = g4[i4] * rsqrtf(v4[i4] + EPS);
        g_c4f[i4] = (b4[i4] - m4[i4]) * s + be4[i4];
    }
}

// ---------------- helpers ---------------------------------------------------
__device__ __forceinline__ float2 ffma2(float2 a, float2 b, float2 c) {
    unsigned long long au, bu, cu, du;
    memcpy(&au, &a, 8); memcpy(&bu, &b, 8); memcpy(&cu, &c, 8);
    asm("fma.rn.f32x2 %0, %1, %2, %3;" : "=l"(du) : "l"(au), "l"(bu), "l"(cu));
    float2 d; memcpy(&d, &du, 8); return d;
}
__device__ __forceinline__ void cp_async16(float* smem_dst, const float* gsrc) {
    unsigned s = (unsigned)__cvta_generic_to_shared(smem_dst);
    asm volatile("cp.async.cg.shared.global [%0], [%1], 16;" :: "r"(s), "l"(gsrc));
}
#define CP_COMMIT()  asm volatile("cp.async.commit_group;")
#define CP_WAIT(n)   asm volatile("cp.async.wait_group %0;" :: "n"(n))

// SMEM (floats):
//   sAT : [0, 18432)       A_T[512][36]  (k-major xs, 8 samples x 4 rows = 32 + pad)
//                          reused after GEMM1: 2 x (64d x 128c) W4 chunks (buf at 0 / 9216)
//   sB  : [18432, 24576)   2 x (16 k x 192 cols) GEMM1 weight tiles (double buf)
//   sATT: [24576, 26656)   8 x 260  att[s][d*4+l]
#define SMF 26656

__global__ void __launch_bounds__(256, 2)
fused_kernel(const float* __restrict__ x, float* __restrict__ out)
{
    extern __shared__ float sm[];
    float* sAT  = sm;
    float* sB   = sm + 18432;
    float* sATT = sm + 24576;

    const int t    = threadIdx.x;
    const int s    = t >> 5;          // warp = local sample 0..7
    const int g    = t & 31;
    const int n0   = blockIdx.x * 8;

    // ---- GEMM1 weight stage loader: 16 k-rows x 192 cols, contiguous in g_W1t
    auto load_stage = [&](int st, int buf) {
        const float* src = g_W1t + st * 16 * 192;
        float* dst = sB + buf * 3072;
        #pragma unroll
        for (int i = 0; i < 3; i++) {
            int q = t + i * 256;                  // [0,768) float4 chunks
            cp_async16(dst + q * 4, src + q * 4);
        }
        CP_COMMIT();
    };
    load_stage(0, 0);

    // ---- Phase 0: one-shot xs gather (strided 2x2 slice) into A_T[c][row]
    {
        const float4* xb = (const float4*)x;
        #pragma unroll
        for (int i = 0; i < 2; i++) {
            int c = t + i * 256;
            #pragma unroll
            for (int ss = 0; ss < 8; ss++) {
                long base = ((long)((n0 + ss) * 512 + c)) * 4;   // float4 idx of x[n][c]
                float4 v0 = __ldg(&xb[base + 0]);                // h=0: w 0..3
                float4 v1 = __ldg(&xb[base + 2]);                // h=2: w 0..3
                *(float4*)&sAT[c * 36 + 4 * ss] = make_float4(v0.x, v0.z, v1.x, v1.z);
            }
        }
    }

    // ---- Phase 1: GEMM1  act[4 rows][192 cols]; thread tile 4 rows x 6 cols
    float2 acc[4][3];
    #pragma unroll
    for (int l = 0; l < 4; l++)
        #pragma unroll
        for (int p = 0; p < 3; p++) acc[l][p] = make_float2(0.f, 0.f);

    for (int st = 0; st < 32; st++) {
        if (st + 1 < 32) {
            load_stage(st + 1, (st + 1) & 1);
            CP_WAIT(1);
        } else {
            CP_WAIT(0);
        }
        __syncthreads();
        const float* bp = sB + (st & 1) * 3072;
        const float* ap = sAT + st * 16 * 36 + 4 * s;
        #pragma unroll 8
        for (int kk = 0; kk < 16; kk++) {
            float4 a  = *(const float4*)&ap[kk * 36];                 // broadcast
            float2 b0 = *(const float2*)&bp[kk * 192 + 2 * g];        // q cols
            float2 b1 = *(const float2*)&bp[kk * 192 + 2 * g + 64];   // k cols
            float2 b2 = *(const float2*)&bp[kk * 192 + 2 * g + 128];  // v cols
            float2 a0 = make_float2(a.x, a.x), a1 = make_float2(a.y, a.y);
            float2 a2 = make_float2(a.z, a.z), a3 = make_float2(a.w, a.w);
            acc[0][0] = ffma2(a0, b0, acc[0][0]);
            acc[0][1] = ffma2(a0, b1, acc[0][1]);
            acc[0][2] = ffma2(a0, b2, acc[0][2]);
            acc[1][0] = ffma2(a1, b0, acc[1][0]);
            acc[1][1] = ffma2(a1, b1, acc[1][1]);
            acc[1][2] = ffma2(a1, b2, acc[1][2]);
            acc[2][0] = ffma2(a2, b0, acc[2][0]);
            acc[2][1] = ffma2(a2, b1, acc[2][1]);
            acc[2][2] = ffma2(a2, b2, acc[2][2]);
            acc[3][0] = ffma2(a3, b0, acc[3][0]);
            acc[3][1] = ffma2(a3, b1, acc[3][1]);
            acc[3][2] = ffma2(a3, b2, acc[3][2]);
        }
        __syncthreads();
    }
    // all warps done with sAT/sB -> reusable

    // ---- W4 chunk loader: chunk cc = 64d x 128c into sAT buf (0 / 9216)
    auto load_w4 = [&](int cc, int buf) {
        float* dst = sAT + buf * 9216;
        #pragma unroll
        for (int i = 0; i < 8; i++) {
            int q = t + i * 256;             // [0,2048): d = q/32, c4 = q%32
            int d = q >> 5, c4 = q & 31;
            cp_async16(dst + d * 128 + c4 * 4, g_W4t + d * 512 + cc * 128 + c4 * 4);
        }
        CP_COMMIT();
    };
    load_w4(0, 0);
    load_w4(1, 1);

    // ---- Phase 2: bias+ReLU, warp-local 4x4 attention (overlaps W4 loads)
    {
        float2 q2[4], k2[4], v2[4];
        float2 bb0 = *(const float2*)&g_b1f[2 * g];
        float2 bb1 = *(const float2*)&g_b1f[2 * g + 64];
        float2 bb2 = *(const float2*)&g_b1f[2 * g + 128];
        #pragma unroll
        for (int l = 0; l < 4; l++) {
            q2[l].x = fmaxf(acc[l][0].x + bb0.x, 0.f);
            q2[l].y = fmaxf(acc[l][0].y + bb0.y, 0.f);
            k2[l].x = fmaxf(acc[l][1].x + bb1.x, 0.f);
            k2[l].y = fmaxf(acc[l][1].y + bb1.y, 0.f);
            v2[l].x = fmaxf(acc[l][2].x + bb2.x, 0.f);
            v2[l].y = fmaxf(acc[l][2].y + bb2.y, 0.f);
        }
        float sc[16];
        #pragma unroll
        for (int l = 0; l < 4; l++)
            #pragma unroll
            for (int m = 0; m < 4; m++)
                sc[l * 4 + m] = q2[l].x * k2[m].x + q2[l].y * k2[m].y;
        #pragma unroll
        for (int off = 16; off > 0; off >>= 1)
            #pragma unroll
            for (int i = 0; i < 16; i++)
                sc[i] += __shfl_xor_sync(0xffffffffu, sc[i], off);

        #pragma unroll
        for (int l = 0; l < 4; l++) {
            float s0 = sc[l*4+0], s1 = sc[l*4+1], s2 = sc[l*4+2], s3 = sc[l*4+3];
            float mx = fmaxf(fmaxf(s0, s1), fmaxf(s2, s3));
            float e0 = __expf(s0 - mx), e1 = __expf(s1 - mx);
            float e2 = __expf(s2 - mx), e3 = __expf(s3 - mx);
            float inv = 1.f / (e0 + e1 + e2 + e3);
            float ax = (e0*v2[0].x + e1*v2[1].x + e2*v2[2].x + e3*v2[3].x) * inv;
            float ay = (e0*v2[0].y + e1*v2[1].y + e2*v2[2].y + e3*v2[3].y) * inv;
            // att_s[s][d][l], warp-local (written & read by same warp)
            sATT[s * 260 + (2*g)   * 4 + l] = ax;
            sATT[s * 260 + (2*g+1) * 4 + l] = ay;
        }
    }

    // ---- Phase 3: GEMM2 + epilogue, 4 chunks of 128 channels, double-buffered
    for (int cc = 0; cc < 4; cc++) {
        if (cc < 3) { CP_WAIT(1); } else { CP_WAIT(0); }
        __syncthreads();   // chunk cc resident in buf cc&1

        const float* wbuf = sAT + (cc & 1) * 9216;
        float2 y[2][4];
        #pragma unroll
        for (int j = 0; j < 2; j++)
            #pragma unroll
            for (int l = 0; l < 4; l++) y[j][l] = make_float2(0.f, 0.f);

        const float* attn = &sATT[s * 260];
        const float* wp = wbuf + 2 * g;
        #pragma unroll 4
        for (int d = 0; d < 64; d++) {
            float4 a  = *(const float4*)&attn[d * 4];     // broadcast
            float2 w0 = *(const float2*)&wp[d * 128];
            float2 w1 = *(const float2*)&wp[d * 128 + 64];
            float2 a0 = make_float2(a.x, a.x), a1 = make_float2(a.y, a.y);
            float2 a2 = make_float2(a.z, a.z), a3 = make_float2(a.w, a.w);
            y[0][0] = ffma2(a0, w0, y[0][0]);
            y[0][1] = ffma2(a1, w0, y[0][1]);
            y[0][2] = ffma2(a2, w0, y[0][2]);
            y[0][3] = ffma2(a3, w0, y[0][3]);
            y[1][0] = ffma2(a0, w1, y[1][0]);
            y[1][1] = ffma2(a1, w1, y[1][1]);
            y[1][2] = ffma2(a2, w1, y[1][2]);
            y[1][3] = ffma2(a3, w1, y[1][3]);
        }
        __syncthreads();               // all warps done reading this buffer
        if (cc + 2 < 4) load_w4(cc + 2, cc & 1);

        // epilogue: out[n,c,h,w] = x[n,c,h,w] + y[c][h] + c4f[c]
        #pragma unroll
        for (int j = 0; j < 2; j++) {
            int cbase = cc * 128 + 64 * j + 2 * g;
            float2 cf = *(const float2*)&g_c4f[cbase];
            const float4* xb = (const float4*)x   + ((long)(n0 + s) * 512 + cbase) * 4;
            float4*       ob = (float4*)out       + ((long)(n0 + s) * 512 + cbase) * 4;
            #pragma unroll
            for (int l = 0; l < 4; l++) {
                float yv = y[j][l].x + cf.x;
                float4 v = __ldg(&xb[l]);
                v.x += yv; v.y += yv; v.z += yv; v.w += yv;
                ob[l] = v;
            }
            #pragma unroll
            for (int l = 0; l < 4; l++) {
                float yv = y[j][l].y + cf.y;
                float4 v = __ldg(&xb[4 + l]);
                v.x += yv; v.y += yv; v.z += yv; v.w += yv;
                ob[4 + l] = v;
            }
        }
    }
}

extern "C" void kernel_launch(void* const* d_in, const int* in_sizes, int n_in,
                              void* d_out, int out_size)
{
    const float* x    = (const float*)d_in[0];
    const float* W123 = (const float*)d_in[1];
    const float* b123 = (const float*)d_in[2];
    const float* g123 = (const float*)d_in[3];
    const float* be123= (const float*)d_in[4];
    const float* m123 = (const float*)d_in[5];
    const float* v123 = (const float*)d_in[6];
    const float* W4   = (const float*)d_in[7];
    const float* b4   = (const float*)d_in[8];
    const float* g4   = (const float*)d_in[9];
    const float* be4  = (const float*)d_in[10];
    const float* m4   = (const float*)d_in[11];
    const float* v4   = (const float*)d_in[12];

    int N = in_sizes[0] / (512 * 16);   // 2048

    prep_kernel<<<515, 256>>>(W123, b123, g123, be123, m123, v123,
                              W4, b4, g4, be4, m4, v4);

    cudaFuncSetAttribute(fused_kernel, cudaFuncAttributeMaxDynamicSharedMemorySize,
                         SMF * 4);
    fused_kernel<<<N / 8, 256, SMF * 4>>>(x, (float*)d_out);
}

// round 6
// speedup vs baseline: 1.3801x; 1.0033x over previous
#include <cuda_runtime.h>
#include <string.h>
#include <stdint.h>

#define EPS 1e-5f

// ---------------- folded-weight scratch (device globals: allowed) ----------
__device__ __align__(16) float g_W1t[512 * 192];     // [c][j], BN1 scale folded (stage-contiguous)
__device__ __align__(16) float g_b1f[192];           // BN1 folded bias
__device__ __align__(16) float g_W4c[4 * 64 * 128];  // [chunk][d][cl], BN2 scale folded
__device__ __align__(16) float g_c4f[512];           // BN2 folded bias

// ---------------- prep: fold BN into weights -------------------------------
__global__ void prep_kernel(const float* __restrict__ W123, const float* __restrict__ b123,
                            const float* __restrict__ g123, const float* __restrict__ be123,
                            const float* __restrict__ m123, const float* __restrict__ v123,
                            const float* __restrict__ W4,   const float* __restrict__ b4,
                            const float* __restrict__ g4,   const float* __restrict__ be4,
                            const float* __restrict__ m4,   const float* __restrict__ v4)
{
    int idx = blockIdx.x * blockDim.x + threadIdx.x;
    if (idx < 512 * 192) {
        int c = idx / 192, j = idx % 192;
        float s = g123[j] * rsqrtf(v123[j] + EPS);
        g_W1t[c * 192 + j] = W123[j * 512 + c] * s;
    }
    int i2 = idx - 512 * 192;
    if (i2 >= 0 && i2 < 192) {
        float s = g123[i2] * rsqrtf(v123[i2] + EPS);
        g_b1f[i2] = (b123[i2] - m123[i2]) * s + be123[i2];
    }
    int i3 = idx - (512 * 192 + 192);
    if (i3 >= 0 && i3 < 4 * 64 * 128) {
        int cc = i3 >> 13;
        int r  = i3 & 8191;
        int d  = r >> 7, cl = r & 127;
        int c  = cc * 128 + cl;
        float s = g4[c] * rsqrtf(v4[c] + EPS);
        g_W4c[i3] = W4[c * 64 + d] * s;
    }
    int i4 = idx - (512 * 192 + 192 + 4 * 64 * 128);
    if (i4 >= 0 && i4 < 512) {
        float s = g4[i4] * rsqrtf(v4[i4] + EPS);
        g_c4f[i4] = (b4[i4] - m4[i4]) * s + be4[i4];
    }
}

// ---------------- helpers ---------------------------------------------------
__device__ __forceinline__ float2 ffma2(float2 a, float2 b, float2 c) {
    unsigned long long au, bu, cu, du;
    memcpy(&au, &a, 8); memcpy(&bu, &b, 8); memcpy(&cu, &c, 8);
    asm("fma.rn.f32x2 %0, %1, %2, %3;" : "=l"(du) : "l"(au), "l"(bu), "l"(cu));
    float2 d; memcpy(&d, &du, 8); return d;
}
__device__ __forceinline__ uint32_t smem_u32(const void* p) {
    uint32_t a;
    asm("{ .reg .u64 t; cvta.to.shared.u64 t, %1; cvt.u32.u64 %0, t; }" : "=r"(a) : "l"(p));
    return a;
}
__device__ __forceinline__ void mbar_init(uint32_t a, uint32_t cnt) {
    asm volatile("mbarrier.init.shared.b64 [%0], %1;" :: "r"(a), "r"(cnt) : "memory");
}
__device__ __forceinline__ void mbar_expect_tx(uint32_t a, uint32_t bytes) {
    asm volatile("mbarrier.arrive.expect_tx.shared.b64 _, [%0], %1;" :: "r"(a), "r"(bytes) : "memory");
}
__device__ __forceinline__ void mbar_wait(uint32_t a, uint32_t parity) {
    asm volatile(
        "{\n\t.reg .pred P;\n\t"
        "WL%=:\n\t"
        "mbarrier.try_wait.parity.acquire.cta.shared::cta.b64 P, [%0], %1, 0x989680;\n\t"
        "@P bra WD%=;\n\t"
        "bra.uni WL%=;\n\t"
        "WD%=:\n\t}"
        :: "r"(a), "r"(parity) : "memory");
}
// 1D bulk async copy gmem -> smem, completion via mbarrier (sm_90 feature)
__device__ __forceinline__ void bulk_g2s(uint32_t dst_smem, const float* gsrc,
                                         uint32_t bytes, uint32_t mbar) {
    asm volatile(
        "cp.async.bulk.shared::cluster.global.mbarrier::complete_tx::bytes [%0], [%1], %2, [%3];"
        :: "r"(dst_smem), "l"(gsrc), "r"(bytes), "r"(mbar) : "memory");
}
#define FENCE_ASYNC() asm volatile("fence.proxy.async.shared::cta;" ::: "memory")

// SMEM (floats):
//   sAT : [0, 34816)       A_T[512][68]  (k-major xs, 16 samples x 4 rows)
//                          reused after GEMM1: 2 x (64d x 128c = 8192) W4 chunks
//   sB  : [34816, 47104)   2 x (32 k x 192 cols) GEMM1 weight tiles (double buf)
//   sATT: [47104, 51264)   16 x 260  att[s][d*4+l]
//   mbar: [51264, 51272)   4 mbarriers (8B each)
#define SMF 51280

__global__ void __launch_bounds__(512, 1)
fused_kernel(const float* __restrict__ x, float* __restrict__ out)
{
    extern __shared__ float sm[];
    float* sAT  = sm;
    float* sB   = sm + 34816;
    float* sATT = sm + 47104;
    const uint32_t smb   = smem_u32(sm);
    const uint32_t smbB  = smb + 34816u * 4u;
    const uint32_t MBAR  = smb + 51264u * 4u;   // MBAR + 8*k, k=0..3

    const int t    = threadIdx.x;
    const int warp = t >> 5;          // 16 warps: warp <-> local sample
    const int g    = t & 31;
    const int n0   = blockIdx.x * 16;

    // ---- init mbarriers, then kick off first two weight stages via bulk TMA
    if (t == 0) {
        mbar_init(MBAR + 0,  1);
        mbar_init(MBAR + 8,  1);
        mbar_init(MBAR + 16, 1);
        mbar_init(MBAR + 24, 1);
    }
    __syncthreads();
    if (t == 0) {
        mbar_expect_tx(MBAR + 0, 24576);
        bulk_g2s(smbB,           g_W1t,        24576, MBAR + 0);
        mbar_expect_tx(MBAR + 8, 24576);
        bulk_g2s(smbB + 24576u,  g_W1t + 6144, 24576, MBAR + 8);
    }

    // ---- Phase 0: gather xs (strided 2x2 slice) into A_T[c][row]
    {
        const float4* xb = (const float4*)x;
        int c = t;                                  // 512 threads <-> 512 channels
        #pragma unroll 4
        for (int i = 0; i < 16; i++) {
            long base = ((long)((n0 + i) * 512 + c)) * 4;   // float4 idx of x[n][c]
            float4 v0 = __ldg(&xb[base + 0]);               // h=0: w 0..3
            float4 v1 = __ldg(&xb[base + 2]);               // h=2: w 0..3
            *(float4*)&sAT[c * 68 + 4 * i] = make_float4(v0.x, v0.z, v1.x, v1.z);
        }
    }
    __syncthreads();   // A_T visible to all warps

    // ---- Phase 1: GEMM1  act[4 rows][192 cols]; thread tile 4 rows x 6 cols
    float2 acc[4][3];
    #pragma unroll
    for (int l = 0; l < 4; l++)
        #pragma unroll
        for (int p = 0; p < 3; p++) acc[l][p] = make_float2(0.f, 0.f);

    for (int st = 0; st < 16; st++) {
        mbar_wait(MBAR + 8u * (st & 1), (st >> 1) & 1);

        const float* bp = sB + (st & 1) * 6144;
        const float* ap = sAT + st * 32 * 68 + 4 * warp;
        #pragma unroll 8
        for (int kk = 0; kk < 32; kk++) {
            float4 a  = *(const float4*)&ap[kk * 68];                 // broadcast
            float2 b0 = *(const float2*)&bp[kk * 192 + 2 * g];        // q cols
            float2 b1 = *(const float2*)&bp[kk * 192 + 2 * g + 64];   // k cols
            float2 b2 = *(const float2*)&bp[kk * 192 + 2 * g + 128];  // v cols
            float2 a0 = make_float2(a.x, a.x), a1 = make_float2(a.y, a.y);
            float2 a2 = make_float2(a.z, a.z), a3 = make_float2(a.w, a.w);
            acc[0][0] = ffma2(a0, b0, acc[0][0]);
            acc[0][1] = ffma2(a0, b1, acc[0][1]);
            acc[0][2] = ffma2(a0, b2, acc[0][2]);
            acc[1][0] = ffma2(a1, b0, acc[1][0]);
            acc[1][1] = ffma2(a1, b1, acc[1][1]);
            acc[1][2] = ffma2(a1, b2, acc[1][2]);
            acc[2][0] = ffma2(a2, b0, acc[2][0]);
            acc[2][1] = ffma2(a2, b1, acc[2][1]);
            acc[2][2] = ffma2(a2, b2, acc[2][2]);
            acc[3][0] = ffma2(a3, b0, acc[3][0]);
            acc[3][1] = ffma2(a3, b1, acc[3][1]);
            acc[3][2] = ffma2(a3, b2, acc[3][2]);
        }
        __syncthreads();   // buffer (st&1) fully consumed by all warps

        if (st + 2 < 16 && t == 0) {
            mbar_expect_tx(MBAR + 8u * (st & 1), 24576);
            bulk_g2s(smbB + 24576u * (st & 1), g_W1t + (st + 2) * 6144, 24576,
                     MBAR + 8u * (st & 1));
        }
    }
    // sAT and sB now dead -> reuse sAT for W4 chunks

    // ---- kick off W4 chunks 0,1 (async proxy writes over old generic writes:
    //      fence generic->async first)
    if (t == 0) {
        FENCE_ASYNC();
        mbar_expect_tx(MBAR + 16, 32768);
        bulk_g2s(smb,              g_W4c,        32768, MBAR + 16);
        mbar_expect_tx(MBAR + 24, 32768);
        bulk_g2s(smb + 32768u,     g_W4c + 8192, 32768, MBAR + 24);
    }

    // ---- Phase 2: bias+ReLU, warp-local 4x4 attention (overlaps W4 arrival)
    {
        float2 q2[4], k2[4], v2[4];
        float2 bb0 = *(const float2*)&g_b1f[2 * g];
        float2 bb1 = *(const float2*)&g_b1f[2 * g + 64];
        float2 bb2 = *(const float2*)&g_b1f[2 * g + 128];
        #pragma unroll
        for (int l = 0; l < 4; l++) {
            q2[l].x = fmaxf(acc[l][0].x + bb0.x, 0.f);
            q2[l].y = fmaxf(acc[l][0].y + bb0.y, 0.f);
            k2[l].x = fmaxf(acc[l][1].x + bb1.x, 0.f);
            k2[l].y = fmaxf(acc[l][1].y + bb1.y, 0.f);
            v2[l].x = fmaxf(acc[l][2].x + bb2.x, 0.f);
            v2[l].y = fmaxf(acc[l][2].y + bb2.y, 0.f);
        }
        float sc[16];
        #pragma unroll
        for (int l = 0; l < 4; l++)
            #pragma unroll
            for (int m = 0; m < 4; m++)
                sc[l * 4 + m] = q2[l].x * k2[m].x + q2[l].y * k2[m].y;
        #pragma unroll
        for (int off = 16; off > 0; off >>= 1)
            #pragma unroll
            for (int i = 0; i < 16; i++)
                sc[i] += __shfl_xor_sync(0xffffffffu, sc[i], off);

        #pragma unroll
        for (int l = 0; l < 4; l++) {
            float s0 = sc[l*4+0], s1 = sc[l*4+1], s2 = sc[l*4+2], s3 = sc[l*4+3];
            float mx = fmaxf(fmaxf(s0, s1), fmaxf(s2, s3));
            float e0 = __expf(s0 - mx), e1 = __expf(s1 - mx);
            float e2 = __expf(s2 - mx), e3 = __expf(s3 - mx);
            float inv = 1.f / (e0 + e1 + e2 + e3);
            float ax = (e0*v2[0].x + e1*v2[1].x + e2*v2[2].x + e3*v2[3].x) * inv;
            float ay = (e0*v2[0].y + e1*v2[1].y + e2*v2[2].y + e3*v2[3].y) * inv;
            // att_s[s][d][l], warp-local (written & read by same warp)
            sATT[warp * 260 + (2*g)   * 4 + l] = ax;
            sATT[warp * 260 + (2*g+1) * 4 + l] = ay;
        }
    }

    // ---- Phase 3: GEMM2 + residual epilogue, 4 chunks of 128 channels
    for (int cc = 0; cc < 4; cc++) {
        mbar_wait(MBAR + 16u + 8u * (cc & 1), (cc >> 1) & 1);

        const float* wbuf = sAT + (cc & 1) * 8192;   // [d][128]
        float2 y[2][4];
        #pragma unroll
        for (int j = 0; j < 2; j++)
            #pragma unroll
            for (int l = 0; l < 4; l++) y[j][l] = make_float2(0.f, 0.f);

        const float* attn = &sATT[warp * 260];
        const float* wp = wbuf + 2 * g;
        #pragma unroll 4
        for (int d = 0; d < 64; d++) {
            float4 a  = *(const float4*)&attn[d * 4];     // broadcast
            float2 w0 = *(const float2*)&wp[d * 128];
            float2 w1 = *(const float2*)&wp[d * 128 + 64];
            float2 a0 = make_float2(a.x, a.x), a1 = make_float2(a.y, a.y);
            float2 a2 = make_float2(a.z, a.z), a3 = make_float2(a.w, a.w);
            y[0][0] = ffma2(a0, w0, y[0][0]);
            y[0][1] = ffma2(a1, w0, y[0][1]);
            y[0][2] = ffma2(a2, w0, y[0][2]);
            y[0][3] = ffma2(a3, w0, y[0][3]);
            y[1][0] = ffma2(a0, w1, y[1][0]);
            y[1][1] = ffma2(a1, w1, y[1][1]);
            y[1][2] = ffma2(a2, w1, y[1][2]);
            y[1][3] = ffma2(a3, w1, y[1][3]);
        }
        __syncthreads();               // all warps done reading this buffer
        if (cc + 2 < 4 && t == 0) {
            mbar_expect_tx(MBAR + 16u + 8u * (cc & 1), 32768);
            bulk_g2s(smb + 32768u * (cc & 1), g_W4c + (cc + 2) * 8192, 32768,
                     MBAR + 16u + 8u * (cc & 1));
        }

        // epilogue: out[n,c,h,w] = x[n,c,h,w] + y[c][h] + c4f[c]
        #pragma unroll
        for (int j = 0; j < 2; j++) {
            int cbase = cc * 128 + 64 * j + 2 * g;
            float2 cf = *(const float2*)&g_c4f[cbase];
            const float4* xb = (const float4*)x   + ((long)(n0 + warp) * 512 + cbase) * 4;
            float4*       ob = (float4*)out       + ((long)(n0 + warp) * 512 + cbase) * 4;
            #pragma unroll
            for (int l = 0; l < 4; l++) {
                float yv = y[j][l].x + cf.x;
                float4 v = __ldg(&xb[l]);
                v.x += yv; v.y += yv; v.z += yv; v.w += yv;
                ob[l] = v;
            }
            #pragma unroll
            for (int l = 0; l < 4; l++) {
                float yv = y[j][l].y + cf.y;
                float4 v = __ldg(&xb[4 + l]);
                v.x += yv; v.y += yv; v.z += yv; v.w += yv;
                ob[4 + l] = v;
            }
        }
    }
}

extern "C" void kernel_launch(void* const* d_in, const int* in_sizes, int n_in,
                              void* d_out, int out_size)
{
    const float* x    = (const float*)d_in[0];
    const float* W123 = (const float*)d_in[1];
    const float* b123 = (const float*)d_in[2];
    const float* g123 = (const float*)d_in[3];
    const float* be123= (const float*)d_in[4];
    const float* m123 = (const float*)d_in[5];
    const float* v123 = (const float*)d_in[6];
    const float* W4   = (const float*)d_in[7];
    const float* b4   = (const float*)d_in[8];
    const float* g4   = (const float*)d_in[9];
    const float* be4  = (const float*)d_in[10];
    const float* m4   = (const float*)d_in[11];
    const float* v4   = (const float*)d_in[12];

    int N = in_sizes[0] / (512 * 16);   // 2048

    prep_kernel<<<515, 256>>>(W123, b123, g123, be123, m123, v123,
                              W4, b4, g4, be4, m4, v4);

    cudaFuncSetAttribute(fused_kernel, cudaFuncAttributeMaxDynamicSharedMemorySize,
                         SMF * 4);
    fused_kernel<<<N / 16, 512, SMF * 4>>>(x, (float*)d_out);
}

// round 7
// speedup vs baseline: 1.3808x; 1.0005x over previous
#include <cuda_runtime.h>
#include <string.h>
#include <stdint.h>

#define EPS 1e-5f

// ---------------- folded-weight scratch (device globals: allowed) ----------
__device__ __align__(16) float g_W1t[512 * 192];     // [c][j], BN1 scale folded
__device__ __align__(16) float g_b1f[192];           // BN1 folded bias
__device__ __align__(16) float g_W4t[64 * 512];      // [d][c], BN2 scale folded
__device__ __align__(16) float g_c4f[512];           // BN2 folded bias

// ---------------- prep: fold BN into weights -------------------------------
__global__ void prep_kernel(const float* __restrict__ W123, const float* __restrict__ b123,
                            const float* __restrict__ g123, const float* __restrict__ be123,
                            const float* __restrict__ m123, const float* __restrict__ v123,
                            const float* __restrict__ W4,   const float* __restrict__ b4,
                            const float* __restrict__ g4,   const float* __restrict__ be4,
                            const float* __restrict__ m4,   const float* __restrict__ v4)
{
    int idx = blockIdx.x * blockDim.x + threadIdx.x;
    if (idx < 512 * 192) {
        int c = idx / 192, j = idx % 192;
        float s = g123[j] * rsqrtf(v123[j] + EPS);
        g_W1t[c * 192 + j] = W123[j * 512 + c] * s;
    }
    int i2 = idx - 512 * 192;
    if (i2 >= 0 && i2 < 192) {
        float s = g123[i2] * rsqrtf(v123[i2] + EPS);
        g_b1f[i2] = (b123[i2] - m123[i2]) * s + be123[i2];
    }
    int i3 = idx - (512 * 192 + 192);
    if (i3 >= 0 && i3 < 64 * 512) {
        int d = i3 / 512, c = i3 % 512;
        float s = g4[c] * rsqrtf(v4[c] + EPS);
        g_W4t[i3] = W4[c * 64 + d] * s;
    }
    int i4 = idx - (512 * 192 + 192 + 64 * 512);
    if (i4 >= 0 && i4 < 512) {
        float s = g4[i4] * rsqrtf(v4[i4] + EPS);
        g_c4f[i4] = (b4[i4] - m4[i4]) * s + be4[i4];
    }
}

// ---------------- helpers ---------------------------------------------------
__device__ __forceinline__ float2 ffma2(float2 a, float2 b, float2 c) {
    unsigned long long au, bu, cu, du;
    memcpy(&au, &a, 8); memcpy(&bu, &b, 8); memcpy(&cu, &c, 8);
    asm("fma.rn.f32x2 %0, %1, %2, %3;" : "=l"(du) : "l"(au), "l"(bu), "l"(cu));
    float2 d; memcpy(&d, &du, 8); return d;
}
__device__ __forceinline__ uint32_t smem_u32(const void* p) {
    uint32_t a;
    asm("{ .reg .u64 t; cvta.to.shared.u64 t, %1; cvt.u32.u64 %0, t; }" : "=r"(a) : "l"(p));
    return a;
}
__device__ __forceinline__ void mbar_init(uint32_t a, uint32_t cnt) {
    asm volatile("mbarrier.init.shared.b64 [%0], %1;" :: "r"(a), "r"(cnt) : "memory");
}
__device__ __forceinline__ void mbar_expect_tx(uint32_t a, uint32_t bytes) {
    asm volatile("mbarrier.arrive.expect_tx.shared.b64 _, [%0], %1;" :: "r"(a), "r"(bytes) : "memory");
}
__device__ __forceinline__ void mbar_wait(uint32_t a, uint32_t parity) {
    asm volatile(
        "{\n\t.reg .pred P;\n\t"
        "WL%=:\n\t"
        "mbarrier.try_wait.parity.acquire.cta.shared::cta.b64 P, [%0], %1, 0x989680;\n\t"
        "@P bra WD%=;\n\t"
        "bra.uni WL%=;\n\t"
        "WD%=:\n\t}"
        :: "r"(a), "r"(parity) : "memory");
}
__device__ __forceinline__ void bulk_g2s(uint32_t dst_smem, const float* gsrc,
                                         uint32_t bytes, uint32_t mbar) {
    asm volatile(
        "cp.async.bulk.shared::cluster.global.mbarrier::complete_tx::bytes [%0], [%1], %2, [%3];"
        :: "r"(dst_smem), "l"(gsrc), "r"(bytes), "r"(mbar) : "memory");
}
#define FENCE_ASYNC() asm volatile("fence.proxy.async.shared::cta;" ::: "memory")

// SMEM (floats):
//   sAT : [0, 34816)       A_T[512][68]  (k-major xs, 16 samples x 4 rows)
//                          reused after GEMM1: W4s[64][512] = 32768 floats
//   sB  : [34816, 47104)   2 x (32 k x 192 cols) GEMM1 weight tiles (double buf)
//                          reused after GEMM1: act[64][192] = 12288 floats
//   sATT: [47104, 51264)   16 x 260  att[s][d*4+l]
//   mbar: [51264, ...)     3 mbarriers
#define SMF 51280

__global__ void __launch_bounds__(768, 1)
fused_kernel(const float* __restrict__ x, float* __restrict__ out)
{
    extern __shared__ float sm[];
    float* sAT  = sm;                  // later: W4s
    float* sB   = sm + 34816;          // later: act
    float* sATT = sm + 47104;
    const uint32_t smb  = smem_u32(sm);
    const uint32_t smbB = smb + 34816u * 4u;
    const uint32_t MBAR = smb + 51264u * 4u;

    const int t    = threadIdx.x;
    const int warp = t >> 5;           // 24 warps
    const int lane = t & 31;
    const int rh   = warp & 1;         // row-half (32 rows each)
    const int cg   = warp >> 1;        // col-group 0..11 (16 cols each)
    const int n0   = blockIdx.x * 16;

    if (t == 0) {
        mbar_init(MBAR + 0,  1);
        mbar_init(MBAR + 8,  1);
        mbar_init(MBAR + 16, 1);
    }
    __syncthreads();
    if (t == 0) {
        mbar_expect_tx(MBAR + 0, 24576);
        bulk_g2s(smbB,          g_W1t,        24576, MBAR + 0);
        mbar_expect_tx(MBAR + 8, 24576);
        bulk_g2s(smbB + 24576u, g_W1t + 6144, 24576, MBAR + 8);
    }

    // ---- Phase 0: gather xs (strided 2x2 slice) into A_T[c][row], row=4*i+l
    {
        const float4* xb = (const float4*)x;
        for (int idx = t; idx < 8192; idx += 768) {
            int c = idx & 511, i = idx >> 9;
            long base = ((long)((n0 + i) * 512 + c)) * 4;
            float4 v0 = __ldg(&xb[base + 0]);               // h=0: w 0..3
            float4 v1 = __ldg(&xb[base + 2]);               // h=2: w 0..3
            *(float4*)&sAT[c * 68 + 4 * i] = make_float4(v0.x, v0.z, v1.x, v1.z);
        }
    }
    __syncthreads();

    // ---- Phase 1: GEMM1  out[64 rows][192 cols]; warp tile 32r x 16c,
    //      lane grid 8x4, thread tile 4r x 4c; both loads LDS.128 conflict-free
    float2 acc[4][2];
    #pragma unroll
    for (int r = 0; r < 4; r++) {
        acc[r][0] = make_float2(0.f, 0.f);
        acc[r][1] = make_float2(0.f, 0.f);
    }
    const int r0 = rh * 32 + (lane >> 2) * 4;     // first of 4 consecutive rows
    const int j0 = cg * 16 + (lane & 3) * 4;      // first of 4 consecutive cols

    for (int st = 0; st < 16; st++) {
        mbar_wait(MBAR + 8u * (st & 1), (st >> 1) & 1);

        const float* bbase = sB + (st & 1) * 6144 + j0;
        const float* abase = sAT + (st * 32) * 68 + r0;
        #pragma unroll 8
        for (int kk = 0; kk < 32; kk++) {
            float4 a = *(const float4*)&abase[kk * 68];     // 8x16B, quad-bcast: 1 wf
            float4 b = *(const float4*)&bbase[kk * 192];    // 4x16B, 8-lane bcast: 1 wf
            float2 b01 = make_float2(b.x, b.y), b23 = make_float2(b.z, b.w);
            acc[0][0] = ffma2(make_float2(a.x, a.x), b01, acc[0][0]);
            acc[0][1] = ffma2(make_float2(a.x, a.x), b23, acc[0][1]);
            acc[1][0] = ffma2(make_float2(a.y, a.y), b01, acc[1][0]);
            acc[1][1] = ffma2(make_float2(a.y, a.y), b23, acc[1][1]);
            acc[2][0] = ffma2(make_float2(a.z, a.z), b01, acc[2][0]);
            acc[2][1] = ffma2(make_float2(a.z, a.z), b23, acc[2][1]);
            acc[3][0] = ffma2(make_float2(a.w, a.w), b01, acc[3][0]);
            acc[3][1] = ffma2(make_float2(a.w, a.w), b23, acc[3][1]);
        }
        __syncthreads();   // buffer (st&1) fully consumed

        if (st + 2 < 16 && t == 0) {
            mbar_expect_tx(MBAR + 8u * (st & 1), 24576);
            bulk_g2s(smbB + 24576u * (st & 1), g_W1t + (st + 2) * 6144, 24576,
                     MBAR + 8u * (st & 1));
        }
    }
    // sAT & sB dead. Kick off full W4 load into old sAT region.
    if (t == 0) {
        FENCE_ASYNC();
        mbar_expect_tx(MBAR + 16, 131072);
        bulk_g2s(smb, g_W4t, 131072, MBAR + 16);
    }

    // ---- act = relu(acc + bias) -> act[64][192] in old sB region
    float* act = sB;
    {
        float4 bias = __ldg((const float4*)&g_b1f[j0]);
        #pragma unroll
        for (int r = 0; r < 4; r++) {
            float4 o;
            o.x = fmaxf(acc[r][0].x + bias.x, 0.f);
            o.y = fmaxf(acc[r][0].y + bias.y, 0.f);
            o.z = fmaxf(acc[r][1].x + bias.z, 0.f);
            o.w = fmaxf(acc[r][1].y + bias.w, 0.f);
            *(float4*)&act[(r0 + r) * 192 + j0] = o;
        }
    }
    __syncthreads();   // act complete

    // ---- Phase 2: warp-local 4x4 attention (warps 0..15, warp = sample)
    if (warp < 16) {
        const int s = warp, g = lane;
        float2 q2[4], k2[4], v2[4];
        #pragma unroll
        for (int l = 0; l < 4; l++) {
            const float* ar = act + (4 * s + l) * 192;
            q2[l] = *(const float2*)&ar[2 * g];
            k2[l] = *(const float2*)&ar[2 * g + 64];
            v2[l] = *(const float2*)&ar[2 * g + 128];
        }
        float sc[16];
        #pragma unroll
        for (int l = 0; l < 4; l++)
            #pragma unroll
            for (int m = 0; m < 4; m++)
                sc[l * 4 + m] = q2[l].x * k2[m].x + q2[l].y * k2[m].y;
        #pragma unroll
        for (int off = 16; off > 0; off >>= 1)
            #pragma unroll
            for (int i = 0; i < 16; i++)
                sc[i] += __shfl_xor_sync(0xffffffffu, sc[i], off);

        #pragma unroll
        for (int l = 0; l < 4; l++) {
            float s0 = sc[l*4+0], s1 = sc[l*4+1], s2 = sc[l*4+2], s3 = sc[l*4+3];
            float mx = fmaxf(fmaxf(s0, s1), fmaxf(s2, s3));
            float e0 = __expf(s0 - mx), e1 = __expf(s1 - mx);
            float e2 = __expf(s2 - mx), e3 = __expf(s3 - mx);
            float inv = 1.f / (e0 + e1 + e2 + e3);
            float ax = (e0*v2[0].x + e1*v2[1].x + e2*v2[2].x + e3*v2[3].x) * inv;
            float ay = (e0*v2[0].y + e1*v2[1].y + e2*v2[2].y + e3*v2[3].y) * inv;
            sATT[s * 260 + (2*g)   * 4 + l] = ax;
            sATT[s * 260 + (2*g+1) * 4 + l] = ay;
        }
    }
    __syncthreads();          // sATT complete
    mbar_wait(MBAR + 16, 0);  // W4s resident in old sAT region

    // ---- Phase 3: GEMM2 + residual epilogue. 64 tasks (16 samples x 4 chunks)
    //      over 24 warps; lane owns 4 consecutive cols -> LDS.128 conflict-free.
    const float* W4s = sm;
    for (int task = warp; task < 64; task += 24) {
        const int s  = task & 15;
        const int cc = task >> 4;
        const int c0 = cc * 128 + lane * 4;

        float2 y2[4][2];
        #pragma unroll
        for (int cp = 0; cp < 4; cp++) {
            y2[cp][0] = make_float2(0.f, 0.f);
            y2[cp][1] = make_float2(0.f, 0.f);
        }
        const float* attn = sATT + s * 260;
        const float* wp   = W4s + c0;
        #pragma unroll 4
        for (int d = 0; d < 64; d++) {
            float4 av = *(const float4*)&attn[d * 4];    // bcast: 1 wf
            float4 wv = *(const float4*)&wp[d * 512];    // 32x16B contig: 4 wf
            float2 a01 = make_float2(av.x, av.y), a23 = make_float2(av.z, av.w);
            y2[0][0] = ffma2(a01, make_float2(wv.x, wv.x), y2[0][0]);
            y2[0][1] = ffma2(a23, make_float2(wv.x, wv.x), y2[0][1]);
            y2[1][0] = ffma2(a01, make_float2(wv.y, wv.y), y2[1][0]);
            y2[1][1] = ffma2(a23, make_float2(wv.y, wv.y), y2[1][1]);
            y2[2][0] = ffma2(a01, make_float2(wv.z, wv.z), y2[2][0]);
            y2[2][1] = ffma2(a23, make_float2(wv.z, wv.z), y2[2][1]);
            y2[3][0] = ffma2(a01, make_float2(wv.w, wv.w), y2[3][0]);
            y2[3][1] = ffma2(a23, make_float2(wv.w, wv.w), y2[3][1]);
        }

        // epilogue: out[n,c,l,0..3] = x + y[c][l] + c4f[c]
        float4 cf = __ldg((const float4*)&g_c4f[c0]);
        const float* cfp = &cf.x;
        #pragma unroll
        for (int cp = 0; cp < 4; cp++) {
            float yv[4] = { y2[cp][0].x, y2[cp][0].y, y2[cp][1].x, y2[cp][1].y };
            long base = ((long)(n0 + s) * 512 + c0 + cp) * 4;   // float4 index
            const float4* xb = (const float4*)x + base;
            float4*       ob = (float4*)out     + base;
            #pragma unroll
            for (int l = 0; l < 4; l++) {
                float v4v = yv[l] + cfp[cp];
                float4 v = __ldg(&xb[l]);
                v.x += v4v; v.y += v4v; v.z += v4v; v.w += v4v;
                ob[l] = v;
            }
        }
    }
}

extern "C" void kernel_launch(void* const* d_in, const int* in_sizes, int n_in,
                              void* d_out, int out_size)
{
    const float* x    = (const float*)d_in[0];
    const float* W123 = (const float*)d_in[1];
    const float* b123 = (const float*)d_in[2];
    const float* g123 = (const float*)d_in[3];
    const float* be123= (const float*)d_in[4];
    const float* m123 = (const float*)d_in[5];
    const float* v123 = (const float*)d_in[6];
    const float* W4   = (const float*)d_in[7];
    const float* b4   = (const float*)d_in[8];
    const float* g4   = (const float*)d_in[9];
    const float* be4  = (const float*)d_in[10];
    const float* m4   = (const float*)d_in[11];
    const float* v4   = (const float*)d_in[12];

    int N = in_sizes[0] / (512 * 16);   // 2048

    prep_kernel<<<515, 256>>>(W123, b123, g123, be123, m123, v123,
                              W4, b4, g4, be4, m4, v4);

    cudaFuncSetAttribute(fused_kernel, cudaFuncAttributeMaxDynamicSharedMemorySize,
                         SMF * 4);
    fused_kernel<<<N / 16, 768, SMF * 4>>>(x, (float*)d_out);
}

// round 8
// speedup vs baseline: 1.8290x; 1.3246x over previous
#include <cuda_runtime.h>
#include <string.h>
#include <stdint.h>

#define EPS 1e-5f

// ---------------- folded-weight scratch (device globals: allowed) ----------
__device__ __align__(16) float g_W1t[512 * 192];     // [c][j], BN1 scale folded
__device__ __align__(16) float g_b1f[192];           // BN1 folded bias
__device__ __align__(16) float g_W4t[64 * 512];      // [d][c], BN2 scale folded
__device__ __align__(16) float g_c4f[512];           // BN2 folded bias

// ---------------- prep: fold BN into weights -------------------------------
__global__ void prep_kernel(const float* __restrict__ W123, const float* __restrict__ b123,
                            const float* __restrict__ g123, const float* __restrict__ be123,
                            const float* __restrict__ m123, const float* __restrict__ v123,
                            const float* __restrict__ W4,   const float* __restrict__ b4,
                            const float* __restrict__ g4,   const float* __restrict__ be4,
                            const float* __restrict__ m4,   const float* __restrict__ v4)
{
    int idx = blockIdx.x * blockDim.x + threadIdx.x;
    if (idx < 512 * 192) {
        int c = idx / 192, j = idx % 192;
        float s = g123[j] * rsqrtf(v123[j] + EPS);
        g_W1t[c * 192 + j] = W123[j * 512 + c] * s;
    }
    int i2 = idx - 512 * 192;
    if (i2 >= 0 && i2 < 192) {
        float s = g123[i2] * rsqrtf(v123[i2] + EPS);
        g_b1f[i2] = (b123[i2] - m123[i2]) * s + be123[i2];
    }
    int i3 = idx - (512 * 192 + 192);
    if (i3 >= 0 && i3 < 64 * 512) {
        int d = i3 / 512, c = i3 % 512;
        float s = g4[c] * rsqrtf(v4[c] + EPS);
        g_W4t[i3] = W4[c * 64 + d] * s;
    }
    int i4 = idx - (512 * 192 + 192 + 64 * 512);
    if (i4 >= 0 && i4 < 512) {
        float s = g4[i4] * rsqrtf(v4[i4] + EPS);
        g_c4f[i4] = (b4[i4] - m4[i4]) * s + be4[i4];
    }
}

// ---------------- helpers ---------------------------------------------------
__device__ __forceinline__ float2 ffma2(float2 a, float2 b, float2 c) {
    unsigned long long au, bu, cu, du;
    memcpy(&au, &a, 8); memcpy(&bu, &b, 8); memcpy(&cu, &c, 8);
    asm("fma.rn.f32x2 %0, %1, %2, %3;" : "=l"(du) : "l"(au), "l"(bu), "l"(cu));
    float2 d; memcpy(&d, &du, 8); return d;
}
__device__ __forceinline__ uint32_t smem_u32(const void* p) {
    uint32_t a;
    asm("{ .reg .u64 t; cvta.to.shared.u64 t, %1; cvt.u32.u64 %0, t; }" : "=r"(a) : "l"(p));
    return a;
}
__device__ __forceinline__ void mbar_init(uint32_t a, uint32_t cnt) {
    asm volatile("mbarrier.init.shared.b64 [%0], %1;" :: "r"(a), "r"(cnt) : "memory");
}
__device__ __forceinline__ void mbar_expect_tx(uint32_t a, uint32_t bytes) {
    asm volatile("mbarrier.arrive.expect_tx.shared.b64 _, [%0], %1;" :: "r"(a), "r"(bytes) : "memory");
}
__device__ __forceinline__ void mbar_wait(uint32_t a, uint32_t parity) {
    asm volatile(
        "{\n\t.reg .pred P;\n\t"
        "WL%=:\n\t"
        "mbarrier.try_wait.parity.acquire.cta.shared::cta.b64 P, [%0], %1, 0x989680;\n\t"
        "@P bra WD%=;\n\t"
        "bra.uni WL%=;\n\t"
        "WD%=:\n\t}"
        :: "r"(a), "r"(parity) : "memory");
}
__device__ __forceinline__ void bulk_g2s(uint32_t dst_smem, const float* gsrc,
                                         uint32_t bytes, uint32_t mbar) {
    asm volatile(
        "cp.async.bulk.shared::cluster.global.mbarrier::complete_tx::bytes [%0], [%1], %2, [%3];"
        :: "r"(dst_smem), "l"(gsrc), "r"(bytes), "r"(mbar) : "memory");
}
#define FENCE_ASYNC() asm volatile("fence.proxy.async.shared::cta;" ::: "memory")

// SMEM (floats):
//   sAT : [0, 34816)       A_T[512][68]; reused after GEMM1: W4s[64][512]
//   sB  : [34816, 47104)   2 x (32k x 192c) weight tiles; reused: act[64][192],
//                          then yS[16][513] (8208 floats)
//   sATT: [47104, 51264)   16 x 260
//   mbar: [51264, ...)     3 mbarriers
#define SMF 51280

__global__ void __launch_bounds__(768, 1)
fused_kernel(const float* __restrict__ x, float* __restrict__ out)
{
    extern __shared__ float sm[];
    float* sAT  = sm;                  // later: W4s
    float* sB   = sm + 34816;          // later: act, then yS
    float* sATT = sm + 47104;
    const uint32_t smb  = smem_u32(sm);
    const uint32_t smbB = smb + 34816u * 4u;
    const uint32_t MBAR = smb + 51264u * 4u;

    const int t    = threadIdx.x;
    const int warp = t >> 5;           // 24 warps
    const int lane = t & 31;
    const int rh   = warp & 1;
    const int cg1  = warp >> 1;        // GEMM1 col-group 0..11
    const int n0   = blockIdx.x * 16;

    if (t == 0) {
        mbar_init(MBAR + 0,  1);
        mbar_init(MBAR + 8,  1);
        mbar_init(MBAR + 16, 1);
    }
    __syncthreads();
    if (t == 0) {
        mbar_expect_tx(MBAR + 0, 24576);
        bulk_g2s(smbB,          g_W1t,        24576, MBAR + 0);
        mbar_expect_tx(MBAR + 8, 24576);
        bulk_g2s(smbB + 24576u, g_W1t + 6144, 24576, MBAR + 8);
    }

    // ---- Phase 0: gather xs (strided 2x2 slice) into A_T[c][row], row=4*i+l
    {
        const float4* xb = (const float4*)x;
        for (int idx = t; idx < 8192; idx += 768) {
            int c = idx & 511, i = idx >> 9;
            long base = ((long)((n0 + i) * 512 + c)) * 4;
            float4 v0 = __ldg(&xb[base + 0]);               // h=0: w 0..3
            float4 v1 = __ldg(&xb[base + 2]);               // h=2: w 0..3
            *(float4*)&sAT[c * 68 + 4 * i] = make_float4(v0.x, v0.z, v1.x, v1.z);
        }
    }
    __syncthreads();

    // ---- Phase 1: GEMM1  [64 rows][192 cols]; warp 32r x 16c; LDS.128 only
    float2 acc[4][2];
    #pragma unroll
    for (int r = 0; r < 4; r++) {
        acc[r][0] = make_float2(0.f, 0.f);
        acc[r][1] = make_float2(0.f, 0.f);
    }
    const int r0 = rh * 32 + (lane >> 2) * 4;
    const int j0 = cg1 * 16 + (lane & 3) * 4;

    for (int st = 0; st < 16; st++) {
        mbar_wait(MBAR + 8u * (st & 1), (st >> 1) & 1);

        const float* bbase = sB + (st & 1) * 6144 + j0;
        const float* abase = sAT + (st * 32) * 68 + r0;
        #pragma unroll 8
        for (int kk = 0; kk < 32; kk++) {
            float4 a = *(const float4*)&abase[kk * 68];
            float4 b = *(const float4*)&bbase[kk * 192];
            float2 b01 = make_float2(b.x, b.y), b23 = make_float2(b.z, b.w);
            acc[0][0] = ffma2(make_float2(a.x, a.x), b01, acc[0][0]);
            acc[0][1] = ffma2(make_float2(a.x, a.x), b23, acc[0][1]);
            acc[1][0] = ffma2(make_float2(a.y, a.y), b01, acc[1][0]);
            acc[1][1] = ffma2(make_float2(a.y, a.y), b23, acc[1][1]);
            acc[2][0] = ffma2(make_float2(a.z, a.z), b01, acc[2][0]);
            acc[2][1] = ffma2(make_float2(a.z, a.z), b23, acc[2][1]);
            acc[3][0] = ffma2(make_float2(a.w, a.w), b01, acc[3][0]);
            acc[3][1] = ffma2(make_float2(a.w, a.w), b23, acc[3][1]);
        }
        __syncthreads();

        if (st + 2 < 16 && t == 0) {
            mbar_expect_tx(MBAR + 8u * (st & 1), 24576);
            bulk_g2s(smbB + 24576u * (st & 1), g_W1t + (st + 2) * 6144, 24576,
                     MBAR + 8u * (st & 1));
        }
    }
    // sAT & sB dead. Kick off full W4 load into old sAT region.
    if (t == 0) {
        FENCE_ASYNC();
        mbar_expect_tx(MBAR + 16, 131072);
        bulk_g2s(smb, g_W4t, 131072, MBAR + 16);
    }

    // ---- act = relu(acc + bias) -> act[64][192] in old sB region
    float* act = sB;
    {
        float4 bias = __ldg((const float4*)&g_b1f[j0]);
        #pragma unroll
        for (int r = 0; r < 4; r++) {
            float4 o;
            o.x = fmaxf(acc[r][0].x + bias.x, 0.f);
            o.y = fmaxf(acc[r][0].y + bias.y, 0.f);
            o.z = fmaxf(acc[r][1].x + bias.z, 0.f);
            o.w = fmaxf(acc[r][1].y + bias.w, 0.f);
            *(float4*)&act[(r0 + r) * 192 + j0] = o;
        }
    }
    __syncthreads();   // act complete

    // ---- Phase 2: warp-local 4x4 attention (warps 0..15, warp = sample)
    if (warp < 16) {
        const int s = warp, g = lane;
        float2 q2[4], k2[4], v2[4];
        #pragma unroll
        for (int l = 0; l < 4; l++) {
            const float* ar = act + (4 * s + l) * 192;
            q2[l] = *(const float2*)&ar[2 * g];
            k2[l] = *(const float2*)&ar[2 * g + 64];
            v2[l] = *(const float2*)&ar[2 * g + 128];
        }
        float sc[16];
        #pragma unroll
        for (int l = 0; l < 4; l++)
            #pragma unroll
            for (int m = 0; m < 4; m++)
                sc[l * 4 + m] = q2[l].x * k2[m].x + q2[l].y * k2[m].y;
        #pragma unroll
        for (int off = 16; off > 0; off >>= 1)
            #pragma unroll
            for (int i = 0; i < 16; i++)
                sc[i] += __shfl_xor_sync(0xffffffffu, sc[i], off);

        #pragma unroll
        for (int l = 0; l < 4; l++) {
            float s0 = sc[l*4+0], s1 = sc[l*4+1], s2 = sc[l*4+2], s3 = sc[l*4+3];
            float mx = fmaxf(fmaxf(s0, s1), fmaxf(s2, s3));
            float e0 = __expf(s0 - mx), e1 = __expf(s1 - mx);
            float e2 = __expf(s2 - mx), e3 = __expf(s3 - mx);
            float inv = 1.f / (e0 + e1 + e2 + e3);
            float ax = (e0*v2[0].x + e1*v2[1].x + e2*v2[2].x + e3*v2[3].x) * inv;
            float ay = (e0*v2[0].y + e1*v2[1].y + e2*v2[2].y + e3*v2[3].y) * inv;
            sATT[s * 260 + (2*g)   * 4 + l] = ax;
            sATT[s * 260 + (2*g+1) * 4 + l] = ay;
        }
    }
    __syncthreads();          // sATT complete; act dead -> yS region
    mbar_wait(MBAR + 16, 0);  // W4s resident

    // ---- Phase 3: GEMM2 + coalesced epilogue, 4 chunks of 128 channels
    // compute: warps 0..15; warp w covers channels cc*128 + w*8 .. +8, all 16
    // samples. lane: s = lane&15, cgr = lane>>4 (channel quad).
    // yS[s][f] (stride 513), f = c_local*4 + l; c4f folded in.
    const float* W4s = sm;
    float* yS = sB;
    const int sI  = lane & 15;
    const int cgr = lane >> 4;

    for (int cc = 0; cc < 4; cc++) {
        if (warp < 16) {
            const int cb  = cc * 128 + warp * 8 + cgr * 4;   // 4 consecutive c
            float2 y01[4], y23[4];
            #pragma unroll
            for (int cp = 0; cp < 4; cp++) {
                y01[cp] = make_float2(0.f, 0.f);
                y23[cp] = make_float2(0.f, 0.f);
            }
            const float* attn = sATT + sI * 260;
            const float* wp   = W4s + cb;
            #pragma unroll 4
            for (int d = 0; d < 64; d++) {
                float4 av = *(const float4*)&attn[d * 4];      // 16 distinct, 2wf
                float4 wv = *(const float4*)&wp[d * 512];      // 2 distinct, 1wf
                float2 a01 = make_float2(av.x, av.y), a23 = make_float2(av.z, av.w);
                const float* wvp = &wv.x;
                #pragma unroll
                for (int cp = 0; cp < 4; cp++) {
                    float2 wb = make_float2(wvp[cp], wvp[cp]);
                    y01[cp] = ffma2(a01, wb, y01[cp]);
                    y23[cp] = ffma2(a23, wb, y23[cp]);
                }
            }
            float4 cf = __ldg((const float4*)&g_c4f[cb]);
            const float* cfp = &cf.x;
            const int fb = (warp * 8 + cgr * 4) * 4;           // f base (c_local*4)
            #pragma unroll
            for (int cp = 0; cp < 4; cp++) {
                float* yp = &yS[sI * 513 + fb + cp * 4];
                yp[0] = y01[cp].x + cfp[cp];
                yp[1] = y01[cp].y + cfp[cp];
                yp[2] = y23[cp].x + cfp[cp];
                yp[3] = y23[cp].y + cfp[cp];
            }
        }
        __syncthreads();   // yS ready

        // coalesced epilogue: 256 units; unit = (sample s, 512B slice i)
        for (int u = warp; u < 256; u += 24) {
            const int s = u >> 4, i = u & 15;
            const int f = i * 32 + lane;              // float4 idx in 8KB block
            float yv = yS[s * 513 + f];
            long b4i = ((long)(n0 + s) * 512 + cc * 128) * 4 + f;
            float4 v = __ldg(&((const float4*)x)[b4i]);
            v.x += yv; v.y += yv; v.z += yv; v.w += yv;
            ((float4*)out)[b4i] = v;
        }
        __syncthreads();   // yS consumed before next chunk overwrites
    }
}

extern "C" void kernel_launch(void* const* d_in, const int* in_sizes, int n_in,
                              void* d_out, int out_size)
{
    const float* x    = (const float*)d_in[0];
    const float* W123 = (const float*)d_in[1];
    const float* b123 = (const float*)d_in[2];
    const float* g123 = (const float*)d_in[3];
    const float* be123= (const float*)d_in[4];
    const float* m123 = (const float*)d_in[5];
    const float* v123 = (const float*)d_in[6];
    const float* W4   = (const float*)d_in[7];
    const float* b4   = (const float*)d_in[8];
    const float* g4   = (const float*)d_in[9];
    const float* be4  = (const float*)d_in[10];
    const float* m4   = (const float*)d_in[11];
    const float* v4   = (const float*)d_in[12];

    int N = in_sizes[0] / (512 * 16);   // 2048

    prep_kernel<<<515, 256>>>(W123, b123, g123, be123, m123, v123,
                              W4, b4, g4, be4, m4, v4);

    cudaFuncSetAttribute(fused_kernel, cudaFuncAttributeMaxDynamicSharedMemorySize,
                         SMF * 4);
    fused_kernel<<<N / 16, 768, SMF * 4>>>(x, (float*)d_out);
}